// round 4
// baseline (speedup 1.0000x reference)
#include <cuda_runtime.h>
#include <cuda_bf16.h>

// social_stgcn_46462956208716
//
// The reference ends with log_softmax over a length-1 axis:
//     out = gcn_conv(h, edge_index, W2, b2)   # [16384, 1]
//     return jax.nn.log_softmax(out, axis=1)  # x - logsumexp([x]) == 0
// For any finite input this is identically zero; all inputs are finite.
// Output = zeros([16384, 1]) exactly.
//
// Session state: kernel node 4.61 us, memset node 4.83 us -> floor is graph
// replay + launch latency, not node contents. This version is the minimal-SASS
// kernel: one unconditional STG.128 per thread, no predicate, no tail
// (out_size = 16384 is a multiple of 512 = 128 threads * 4 floats).

__global__ __launch_bounds__(128, 1)
void zero_out_kernel(float4* __restrict__ out) {
    out[blockIdx.x * 128 + threadIdx.x] = make_float4(0.f, 0.f, 0.f, 0.f);
}

__global__ void zero_tail_kernel(float* __restrict__ out, int start, int n) {
    int i = start + blockIdx.x * blockDim.x + threadIdx.x;
    if (i < n) out[i] = 0.f;
}

extern "C" void kernel_launch(void* const* d_in, const int* in_sizes, int n_in,
                              void* d_out, int out_size) {
    (void)d_in; (void)in_sizes; (void)n_in;

    float* out = (float*)d_out;

    // Main body: 128 threads/CTA, 4 floats/thread -> 512 floats per CTA.
    int full = out_size / 512;                 // 16384/512 = 32 CTAs
    if (full > 0) {
        zero_out_kernel<<<full, 128>>>((float4*)out);
    }
    int done = full * 512;
    if (done < out_size) {                     // dead for out_size = 16384
        int rem = out_size - done;
        zero_tail_kernel<<<(rem + 127) / 128, 128>>>(out, done, out_size);
    }
}

// round 5
// speedup vs baseline: 1.2222x; 1.2222x over previous
#include <cuda_runtime.h>
#include <cuda_bf16.h>

// social_stgcn_46462956208716
//
// The reference ends with log_softmax over a length-1 axis:
//     out = gcn_conv(h, edge_index, W2, b2)   # [16384, 1]
//     return jax.nn.log_softmax(out, axis=1)  # x - logsumexp([x]) == 0
// For any finite input this is identically zero, and all inputs are finite
// (seeded Gaussians; degree norm guarded by where/max). So the full 2-layer
// GCN is algebraically annihilated: output = zeros([16384, 1]).
//
// Session measurements (all functionally identical zero-writers):
//   R1 16x256 + tail kernel : 4.86 us
//   R2  4x1024 single kernel: 4.61 us   <- best
//   R3 memset node          : 4.83 us
//   R4 32x128 no-predicate  : 5.63 us
// ncu shows DRAM 0.0% in all cases; the measured time is graph-replay +
// launch latency, and the spread is noise. Revert to the best-measured R2
// configuration: single kernel node, 4 CTAs x 1024 threads, one float4 store
// per thread.

__global__ __launch_bounds__(1024, 1)
void zero_out_kernel(float* __restrict__ out, int out_size) {
    int i = blockIdx.x * blockDim.x + threadIdx.x;   // 0..4095
    int i4 = i * 4;
    if (i4 + 3 < out_size) {
        *reinterpret_cast<float4*>(out + i4) = make_float4(0.f, 0.f, 0.f, 0.f);
    } else {
        // tail (dead at runtime for out_size % 4 == 0, kept for generality)
        for (int j = i4; j < out_size; ++j) out[j] = 0.f;
    }
}

extern "C" void kernel_launch(void* const* d_in, const int* in_sizes, int n_in,
                              void* d_out, int out_size) {
    (void)d_in; (void)in_sizes; (void)n_in;

    float* out = (float*)d_out;

    // out_size = 16384 -> 4096 float4 stores -> 4 CTAs x 1024 threads, one wave.
    int n_vec4 = (out_size + 3) / 4;
    const int threads = 1024;
    int blocks = (n_vec4 + threads - 1) / threads;
    if (blocks < 1) blocks = 1;
    zero_out_kernel<<<blocks, threads>>>(out, out_size);
}